// round 5
// baseline (speedup 1.0000x reference)
#include <cuda_runtime.h>
#include <cuda_bf16.h>

// SubglacialDrainageSystem: L x = f on a 64x64 grid.
// Block cyclic reduction over the 64-block tridiagonal structure (BD=64).
// R5: k1 is a software-pipelined rank-4 Gauss-Jordan with ONE barrier per
// iteration; the 4x4 pivot-block inverse for the NEXT window is computed
// concurrently by warp 0 (lanes 0-15, shuffle-based GJ) from one-window-ahead
// published data, so no serial region sits between barriers.

#define NBLK 64
#define BD   64
#define BSZ  (BD * BD)

static __device__ float gA [NBLK * BSZ];
static __device__ float gCb[2][NBLK * BSZ];
static __device__ float gBb[2][NBLK * BSZ];
static __device__ float gy [NBLK * BD];
static __device__ float gZC[NBLK * BSZ];
static __device__ float gZB[NBLK * BSZ];
static __device__ float gZy[NBLK * BD];

// ---------------------------------------------------------------------------
// Assembly
// ---------------------------------------------------------------------------
__global__ void assemble_kernel(const float* __restrict__ h,
                                const float* __restrict__ phi,
                                const float* __restrict__ base,
                                const float* __restrict__ over,
                                const float* __restrict__ melt,
                                const float* __restrict__ len,
                                const int*   __restrict__ adj,
                                const int*   __restrict__ io)
{
    int i = blockIdx.x * blockDim.x + threadIdx.x;
    if (i >= NBLK * BD) return;
    int r = i >> 6, a = i & 63;

    float4 z = make_float4(0.f, 0.f, 0.f, 0.f);
    float4* rowA = (float4*)(gA     + r * BSZ + a * BD);
    float4* rowC = (float4*)(gCb[0] + r * BSZ + a * BD);
    float4* rowB = (float4*)(gBb[0] + r * BSZ + a * BD);
#pragma unroll
    for (int b = 0; b < 16; b++) { rowA[b] = z; rowC[b] = z; rowB[b] = z; }

    const bool infl = (io[i] == 1);
    const double hi = (double)h[i];
    const double pi = (double)phi[i];
    double diag = 0.0;
    double cf0 = 0.0, cf1 = 0.0, cf2 = 0.0, cf3 = 0.0;

#pragma unroll
    for (int k = 0; k < 4; k++) {           // 0 north, 1 south, 2 west, 3 east
        int   j = adj[i * 4 + k];
        float L = len[i * 4 + k];
        double cc = 0.0;
        if (j >= 0 && L > 0.0f && !infl) {
            double hf   = 0.5 * (hi + (double)h[j]);
            double dphi = fabs(pi - (double)phi[j]);
            double g    = fmax(dphi, 1e-12) / (double)L;
            cc = -0.01 * pow(hf, 1.25) * (double)L * rsqrt(g);
            diag -= cc;
        }
        if (k == 0) cf0 = cc; else if (k == 1) cf1 = cc;
        else if (k == 2) cf2 = cc; else cf3 = cc;
    }

    gA[r * BSZ + a * BD + a] = infl ? 1.0f : (float)diag;
    if (a > 0)  gA[r * BSZ + a * BD + (a - 1)] = (float)cf2;
    if (a < 63) gA[r * BSZ + a * BD + (a + 1)] = (float)cf3;
    gCb[0][r * BSZ + a * BD + a] = (float)cf0;
    gBb[0][r * BSZ + a * BD + a] = (float)cf1;
    gy[i] = infl ? (float)((double)base[i] - (double)over[i]) : melt[i];
}

// ---------------------------------------------------------------------------
// 16-lane 4x4 Gauss-Jordan inverse. Lane (r,c) = lane r*4+c of warp 0 holds
// A[r][c] in av; returns Inv[r][c]. Lanes 16-31 must not call this.
// ---------------------------------------------------------------------------
__device__ __forceinline__ float gj4_inverse_lane(float av, int r, int c)
{
    const unsigned am = 0xFFFFu;
    float iv = (r == c) ? 1.0f : 0.0f;
#pragma unroll
    for (int p = 0; p < 4; p++) {
        float app = __shfl_sync(am, av, p * 4 + p);
        float apc = __shfl_sync(am, av, p * 4 + c);
        float ipc = __shfl_sync(am, iv, p * 4 + c);
        float arp = __shfl_sync(am, av, r * 4 + p);
        float rinv = __fdividef(1.0f, app);
        if (r == p) { av = apc * rinv;          iv = ipc * rinv; }
        else        { float f = arp * rinv; av -= f * apc; iv -= f * ipc; }
    }
    return iv;
}

// ---------------------------------------------------------------------------
// K1: pipelined rank-4 GJ on [A | C | B | y] (64 x 193).
// thread: row = tid&63, group g = tid>>6 owns cols [12g,12g+12) (+192 if g=15)
// Double-buffered smem; exactly one __syncthreads per iteration.
// ---------------------------------------------------------------------------
__global__ void __launch_bounds__(1024, 1)
k1_factor(int s, int parity)
{
    const int j    = s - 1 + 2 * s * blockIdx.x;
    const int row  = threadIdx.x & 63;
    const int g    = threadIdx.x >> 6;
    const int c0   = 12 * g;
    const int lane = threadIdx.x & 31;
    const bool invwarp = (threadIdx.x < 16);      // warp 0, lanes 0-15

    const float* Aj = gA + j * BSZ;
    const float* Cj = gCb[parity] + j * BSZ;
    const float* Bj = gBb[parity] + j * BSZ;

    float m[13];
#pragma unroll
    for (int q = 0; q < 13; q++) {
        int c = c0 + q;
        float v = 0.0f;
        if (q < 12 || g == 15) {
            if      (c < 64)  v = Aj[row * BD + c];
            else if (c < 128) v = Cj[row * BD + (c - 64)];
            else if (c < 192) v = Bj[row * BD + (c - 128)];
            else              v = gy[j * BD + row];
        }
        m[q] = v;
    }

    __shared__ float s_prow[2][4][200];   // pivot rows (raw), double buffered
    __shared__ float s_pcol[2][4][64];    // pivot cols, transposed
    __shared__ float s_pblk[2][4][4];     // NEXT window 4x4 block (raw)
    __shared__ float s_W[2][16];          // P^{-1}, row-major [4r+t]

    // ---- prologue: window 0 data ----------------------------------------
    if (row < 4) {
        *(float4*)&s_prow[0][row][c0]     = make_float4(m[0], m[1], m[2],  m[3]);
        *(float4*)&s_prow[0][row][c0 + 4] = make_float4(m[4], m[5], m[6],  m[7]);
        *(float4*)&s_prow[0][row][c0 + 8] = make_float4(m[8], m[9], m[10], m[11]);
        if (g == 15) s_prow[0][row][192] = m[12];
    }
    if (g == 0) {
#pragma unroll
        for (int q = 0; q < 4; q++) s_pcol[0][q][row] = m[q];
        if (row >= 4 && row < 8) {
#pragma unroll
            for (int t = 0; t < 4; t++) s_pblk[0][row - 4][t] = m[4 + t];
        }
    }
    __syncthreads();
    if (invwarp) {
        int r4 = lane >> 2, ccl = lane & 3;
        float av = s_pcol[0][ccl][r4];               // P[r][c]
        s_W[0][lane] = gj4_inverse_lane(av, r4, ccl);
    }
    __syncthreads();

    // ---- 16 pipelined rank-4 iterations ----------------------------------
    for (int it = 0; it < 16; it++) {
        const int k  = 4 * it;
        const int b  = it & 1;
        const int nb = b ^ 1;
        const int kn = k + 4;
        const bool ispiv = (row >= k) && (row < kn);

        float4 W0 = *(const float4*)&s_W[b][0];
        float4 W1 = *(const float4*)&s_W[b][4];
        float4 W2 = *(const float4*)&s_W[b][8];
        float4 W3 = *(const float4*)&s_W[b][12];

        float u0, u1, u2, u3;
        if (ispiv) {
            int rr = row - k;
            float4 Wr = (rr == 0) ? W0 : (rr == 1) ? W1 : (rr == 2) ? W2 : W3;
            u0 = Wr.x; u1 = Wr.y; u2 = Wr.z; u3 = Wr.w;
        } else {
            float v0 = s_pcol[b][0][row];
            float v1 = s_pcol[b][1][row];
            float v2 = s_pcol[b][2][row];
            float v3 = s_pcol[b][3][row];
            u0 = -(v0 * W0.x + v1 * W1.x + v2 * W2.x + v3 * W3.x);
            u1 = -(v0 * W0.y + v1 * W1.y + v2 * W2.y + v3 * W3.y);
            u2 = -(v0 * W0.z + v1 * W1.z + v2 * W2.z + v3 * W3.z);
            u3 = -(v0 * W0.w + v1 * W1.w + v2 * W2.w + v3 * W3.w);
        }

        // update live chunks (dead A-cols c < k+4 skipped; warp-uniform)
#pragma unroll
        for (int ch = 0; ch < 3; ch++) {
            int cc = c0 + 4 * ch;
            if (cc + 3 >= kn) {
                float4 p0 = *(const float4*)&s_prow[b][0][cc];
                float4 p1 = *(const float4*)&s_prow[b][1][cc];
                float4 p2 = *(const float4*)&s_prow[b][2][cc];
                float4 p3 = *(const float4*)&s_prow[b][3][cc];
                float b0 = ispiv ? 0.0f : m[4 * ch + 0];
                float b1 = ispiv ? 0.0f : m[4 * ch + 1];
                float b2 = ispiv ? 0.0f : m[4 * ch + 2];
                float b3 = ispiv ? 0.0f : m[4 * ch + 3];
                m[4 * ch + 0] = b0 + u0 * p0.x + u1 * p1.x + u2 * p2.x + u3 * p3.x;
                m[4 * ch + 1] = b1 + u0 * p0.y + u1 * p1.y + u2 * p2.y + u3 * p3.y;
                m[4 * ch + 2] = b2 + u0 * p0.z + u1 * p1.z + u2 * p2.z + u3 * p3.z;
                m[4 * ch + 3] = b3 + u0 * p0.w + u1 * p1.w + u2 * p2.w + u3 * p3.w;
            }
        }
        if (g == 15) {
            float py0 = s_prow[b][0][192], py1 = s_prow[b][1][192];
            float py2 = s_prow[b][2][192], py3 = s_prow[b][3][192];
            float bb = ispiv ? 0.0f : m[12];
            m[12] = bb + u0 * py0 + u1 * py1 + u2 * py2 + u3 * py3;
        }

        if (it < 15) {
            // ---- concurrent next-window pivot inverse (warp 0, lanes 0-15)
            if (invwarp) {
                int r4 = lane >> 2, ccl = lane & 3;
                // u for row kn+r4 (non-pivot in window k)
                float v0 = s_pcol[b][0][kn + r4];
                float v1 = s_pcol[b][1][kn + r4];
                float v2 = s_pcol[b][2][kn + r4];
                float v3 = s_pcol[b][3][kn + r4];
                float t0 = -(v0 * W0.x + v1 * W1.x + v2 * W2.x + v3 * W3.x);
                float t1 = -(v0 * W0.y + v1 * W1.y + v2 * W2.y + v3 * W3.y);
                float t2 = -(v0 * W0.z + v1 * W1.z + v2 * W2.z + v3 * W3.z);
                float t3 = -(v0 * W0.w + v1 * W1.w + v2 * W2.w + v3 * W3.w);
                float av = s_pblk[b][r4][ccl]
                         + t0 * s_prow[b][0][kn + ccl]
                         + t1 * s_prow[b][1][kn + ccl]
                         + t2 * s_prow[b][2][kn + ccl]
                         + t3 * s_prow[b][3][kn + ccl];
                s_W[nb][lane] = gj4_inverse_lane(av, r4, ccl);
            }

            // ---- publishes for window kn --------------------------------
            if (row >= kn && row < kn + 4) {          // pivot rows (raw)
                int r2 = row - kn;
                *(float4*)&s_prow[nb][r2][c0]     = make_float4(m[0], m[1], m[2],  m[3]);
                *(float4*)&s_prow[nb][r2][c0 + 4] = make_float4(m[4], m[5], m[6],  m[7]);
                *(float4*)&s_prow[nb][r2][c0 + 8] = make_float4(m[8], m[9], m[10], m[11]);
                if (g == 15) s_prow[nb][r2][192] = m[12];
            }
            {
                int qoff = kn - c0;                   // pivot cols, one group
                if (qoff >= 0 && qoff <= 8) {
#pragma unroll
                    for (int t = 0; t < 4; t++) s_pcol[nb][t][row] = m[qoff + t];
                }
            }
            if (it <= 13) {                           // block for window kn+4
                int k8 = k + 8;
                int qoff2 = k8 - c0;
                if (qoff2 >= 0 && qoff2 <= 8 && row >= k8 && row < k8 + 4) {
#pragma unroll
                    for (int t = 0; t < 4; t++) s_pblk[nb][row - k8][t] = m[qoff2 + t];
                }
            }
        }
        __syncthreads();
    }

    // ---- write Z = [ZC | ZB | Zy] ----------------------------------------
#pragma unroll
    for (int q = 0; q < 13; q++) {
        int c = c0 + q;
        if (q < 12 || g == 15) {
            if      (c >= 64  && c < 128) gZC[j * BSZ + row * BD + (c - 64)]  = m[q];
            else if (c >= 128 && c < 192) gZB[j * BSZ + row * BD + (c - 128)] = m[q];
            else if (c == 192)            gZy[j * BD + row] = m[q];
        }
    }
}

// ---------------------------------------------------------------------------
// K2: Schur updates (unchanged from R4)
// ---------------------------------------------------------------------------
#define K2_SMEM (4 * 64 * 68 * 4)

__global__ void __launch_bounds__(256, 1)
k2_update(int s, int p)
{
    const int i    = 2 * s - 1 + 2 * s * blockIdx.x;
    const int task = blockIdx.y;
    const int jm   = i - s;
    const int jp   = (i + s > 63) ? 63 : (i + s);
    const int tid  = threadIdx.x;

    if (task == 3) {
        __shared__ float sy1[64], sy2[64];
        if (tid < 64) { sy1[tid] = gZy[jm * BD + tid]; sy2[tid] = gZy[jp * BD + tid]; }
        __syncthreads();
        if (tid < 64) {
            float acc = gy[i * BD + tid];
            const float* cp = gCb[p] + i * BSZ + tid * BD;
            const float* bp = gBb[p] + i * BSZ + tid * BD;
#pragma unroll 8
            for (int b = 0; b < 64; b++) acc -= cp[b] * sy1[b] + bp[b] * sy2[b];
            gy[i * BD + tid] = acc;
        }
        return;
    }

    extern __shared__ float sm2[];
    float* P1 = sm2;
    float* Q1 = sm2 + 64 * 68;
    float* P2 = sm2 + 2 * 64 * 68;
    float* Q2 = sm2 + 3 * 64 * 68;

    const float *p1g, *q1g, *p2g = nullptr, *q2g = nullptr;
    if (task == 0) {
        p1g = gCb[p] + i * BSZ;  q1g = gZB + jm * BSZ;
        p2g = gBb[p] + i * BSZ;  q2g = gZC + jp * BSZ;
    } else if (task == 1) {
        p1g = gCb[p] + i * BSZ;  q1g = gZC + jm * BSZ;
    } else {
        p1g = gBb[p] + i * BSZ;  q1g = gZB + jp * BSZ;
    }

    for (int e = tid; e < BSZ; e += 256) {
        int r = e >> 6, c = e & 63;
        P1[r * 68 + c] = p1g[e];
        Q1[r * 68 + c] = q1g[e];
        if (task == 0) { P2[r * 68 + c] = p2g[e]; Q2[r * 68 + c] = q2g[e]; }
    }
    __syncthreads();

    const int r0 = (tid >> 4) << 2;
    const int cc = (tid & 15) << 2;
    float acc[4][4];
#pragma unroll
    for (int u = 0; u < 4; u++)
#pragma unroll
        for (int v = 0; v < 4; v++) acc[u][v] = 0.0f;

    if (task == 0) {
        for (int k = 0; k < 64; k++) {
            float4 b1 = *(const float4*)&Q1[k * 68 + cc];
            float4 b2 = *(const float4*)&Q2[k * 68 + cc];
#pragma unroll
            for (int u = 0; u < 4; u++) {
                float a1 = P1[(r0 + u) * 68 + k];
                float a2 = P2[(r0 + u) * 68 + k];
                acc[u][0] += a1 * b1.x + a2 * b2.x;
                acc[u][1] += a1 * b1.y + a2 * b2.y;
                acc[u][2] += a1 * b1.z + a2 * b2.z;
                acc[u][3] += a1 * b1.w + a2 * b2.w;
            }
        }
        float* dst = gA + i * BSZ;
#pragma unroll
        for (int u = 0; u < 4; u++) {
            float4 o = *(float4*)&dst[(r0 + u) * BD + cc];
            o.x -= acc[u][0]; o.y -= acc[u][1]; o.z -= acc[u][2]; o.w -= acc[u][3];
            *(float4*)&dst[(r0 + u) * BD + cc] = o;
        }
    } else {
        for (int k = 0; k < 64; k++) {
            float4 b1 = *(const float4*)&Q1[k * 68 + cc];
#pragma unroll
            for (int u = 0; u < 4; u++) {
                float a1 = P1[(r0 + u) * 68 + k];
                acc[u][0] += a1 * b1.x;
                acc[u][1] += a1 * b1.y;
                acc[u][2] += a1 * b1.z;
                acc[u][3] += a1 * b1.w;
            }
        }
        float* dst = ((task == 1) ? gCb[p ^ 1] : gBb[p ^ 1]) + i * BSZ;
#pragma unroll
        for (int u = 0; u < 4; u++)
            *(float4*)&dst[(r0 + u) * BD + cc] =
                make_float4(-acc[u][0], -acc[u][1], -acc[u][2], -acc[u][3]);
    }
}

// ---------------------------------------------------------------------------
// Backsub (unchanged)
// ---------------------------------------------------------------------------
__global__ void __launch_bounds__(1024, 1)
backsub_kernel(float* __restrict__ out)
{
    __shared__ float sx[NBLK * BD];
    const int tid = threadIdx.x;
    for (int e = tid; e < NBLK * BD; e += 1024) sx[e] = 0.0f;
    __syncthreads();

    for (int lev = 7; lev >= 1; lev--) {
        int s  = 1 << (lev - 1);
        int ne = (lev == 7) ? 1 : (32 >> (lev - 1));
        for (int idx = tid; idx < ne * 64; idx += 1024) {
            int t = idx >> 6, a = idx & 63;
            int j = s - 1 + 2 * s * t;
            int jm = j - s; if (jm < 0)  jm = 0;
            int jp = j + s; if (jp > 63) jp = 63;
            const float4* zc = (const float4*)(gZC + j * BSZ + a * BD);
            const float4* zb = (const float4*)(gZB + j * BSZ + a * BD);
            float s0 = 0.f, s1 = 0.f, s2 = 0.f, s3 = 0.f;
#pragma unroll
            for (int w = 0; w < 16; w++) {
                float4 c4 = zc[w], b4 = zb[w];
                s0 += c4.x * sx[jm * BD + 4 * w]     + b4.x * sx[jp * BD + 4 * w];
                s1 += c4.y * sx[jm * BD + 4 * w + 1] + b4.y * sx[jp * BD + 4 * w + 1];
                s2 += c4.z * sx[jm * BD + 4 * w + 2] + b4.z * sx[jp * BD + 4 * w + 2];
                s3 += c4.w * sx[jm * BD + 4 * w + 3] + b4.w * sx[jp * BD + 4 * w + 3];
            }
            float acc = gZy[j * BD + a] - (s0 + s1 + s2 + s3);
            sx[j * BD + a]  = acc;
            out[j * BD + a] = acc;
        }
        __syncthreads();
    }
}

// ---------------------------------------------------------------------------
// kernel_launch
// ---------------------------------------------------------------------------
extern "C" void kernel_launch(void* const* d_in, const int* in_sizes, int n_in,
                              void* d_out, int out_size)
{
    const float* h    = (const float*)d_in[0];
    const float* phi  = (const float*)d_in[1];
    const float* base = (const float*)d_in[2];
    const float* over = (const float*)d_in[3];
    const float* melt = (const float*)d_in[4];
    const float* len  = (const float*)d_in[5];
    const int*   adj  = (const int*)  d_in[6];
    const int*   io   = (const int*)  d_in[7];
    float* out = (float*)d_out;

    static int once = []() {
        cudaFuncSetAttribute(k2_update,
                             cudaFuncAttributeMaxDynamicSharedMemorySize,
                             K2_SMEM);
        return 0;
    }();
    (void)once;

    assemble_kernel<<<32, 128>>>(h, phi, base, over, melt, len, adj, io);

    for (int lev = 1; lev <= 6; lev++) {
        int s = 1 << (lev - 1);
        int n = 32 >> (lev - 1);
        int p = (lev - 1) & 1;
        k1_factor<<<n, 1024>>>(s, p);
        k2_update<<<dim3(n, 4), 256, K2_SMEM>>>(s, p);
    }
    k1_factor<<<1, 1024>>>(64, 0);
    backsub_kernel<<<1, 1024>>>(out);
}

// round 6
// speedup vs baseline: 1.1174x; 1.1174x over previous
#include <cuda_runtime.h>
#include <cuda_bf16.h>

// SubglacialDrainageSystem: L x = f on a 64x64 grid.
// Block cyclic reduction over the 64-block tridiagonal structure (BD=64).
// R6: k1 Gauss-Jordan uses 256 threads, each owning a 4-row x 12-col register
// tile -> pivot-row smem loads amortized 4x, ~3x fewer issued instructions.
// Single barrier per iteration; 4x4 pivot inverse pipelined on lanes 0-15.

#define NBLK 64
#define BD   64
#define BSZ  (BD * BD)

static __device__ float gA [NBLK * BSZ];
static __device__ float gCb[2][NBLK * BSZ];
static __device__ float gBb[2][NBLK * BSZ];
static __device__ float gy [NBLK * BD];
static __device__ float gZC[NBLK * BSZ];
static __device__ float gZB[NBLK * BSZ];
static __device__ float gZy[NBLK * BD];

// ---------------------------------------------------------------------------
// Assembly
// ---------------------------------------------------------------------------
__global__ void assemble_kernel(const float* __restrict__ h,
                                const float* __restrict__ phi,
                                const float* __restrict__ base,
                                const float* __restrict__ over,
                                const float* __restrict__ melt,
                                const float* __restrict__ len,
                                const int*   __restrict__ adj,
                                const int*   __restrict__ io)
{
    int i = blockIdx.x * blockDim.x + threadIdx.x;
    if (i >= NBLK * BD) return;
    int r = i >> 6, a = i & 63;

    float4 z = make_float4(0.f, 0.f, 0.f, 0.f);
    float4* rowA = (float4*)(gA     + r * BSZ + a * BD);
    float4* rowC = (float4*)(gCb[0] + r * BSZ + a * BD);
    float4* rowB = (float4*)(gBb[0] + r * BSZ + a * BD);
#pragma unroll
    for (int b = 0; b < 16; b++) { rowA[b] = z; rowC[b] = z; rowB[b] = z; }

    const bool infl = (io[i] == 1);
    const double hi = (double)h[i];
    const double pi = (double)phi[i];
    double diag = 0.0;
    double cf0 = 0.0, cf1 = 0.0, cf2 = 0.0, cf3 = 0.0;

#pragma unroll
    for (int k = 0; k < 4; k++) {           // 0 north, 1 south, 2 west, 3 east
        int   j = adj[i * 4 + k];
        float L = len[i * 4 + k];
        double cc = 0.0;
        if (j >= 0 && L > 0.0f && !infl) {
            double hf   = 0.5 * (hi + (double)h[j]);
            double dphi = fabs(pi - (double)phi[j]);
            double g    = fmax(dphi, 1e-12) / (double)L;
            cc = -0.01 * pow(hf, 1.25) * (double)L * rsqrt(g);
            diag -= cc;
        }
        if (k == 0) cf0 = cc; else if (k == 1) cf1 = cc;
        else if (k == 2) cf2 = cc; else cf3 = cc;
    }

    gA[r * BSZ + a * BD + a] = infl ? 1.0f : (float)diag;
    if (a > 0)  gA[r * BSZ + a * BD + (a - 1)] = (float)cf2;
    if (a < 63) gA[r * BSZ + a * BD + (a + 1)] = (float)cf3;
    gCb[0][r * BSZ + a * BD + a] = (float)cf0;
    gBb[0][r * BSZ + a * BD + a] = (float)cf1;
    gy[i] = infl ? (float)((double)base[i] - (double)over[i]) : melt[i];
}

// ---------------------------------------------------------------------------
// 16-lane 4x4 Gauss-Jordan inverse (lanes 0-15 of warp 0; lane = r*4+c).
// ---------------------------------------------------------------------------
__device__ __forceinline__ float gj4_inverse_lane(float av, int r, int c)
{
    const unsigned am = 0xFFFFu;
    float iv = (r == c) ? 1.0f : 0.0f;
#pragma unroll
    for (int p = 0; p < 4; p++) {
        float app = __shfl_sync(am, av, p * 4 + p);
        float apc = __shfl_sync(am, av, p * 4 + c);
        float ipc = __shfl_sync(am, iv, p * 4 + c);
        float arp = __shfl_sync(am, av, r * 4 + p);
        float rinv = __fdividef(1.0f, app);
        if (r == p) { av = apc * rinv;          iv = ipc * rinv; }
        else        { float f = arp * rinv; av -= f * apc; iv -= f * ipc; }
    }
    return iv;
}

// ---------------------------------------------------------------------------
// K1: pipelined rank-4 GJ on [A | C | B | y] (64 x 193), 256 threads.
// cg = tid>>4 owns cols [12cg,12cg+12) (+col 192 if cg==15);
// rg = tid&15 owns rows [4rg,4rg+4). Register tile m[4][12] (+my[4]).
// One __syncthreads per iteration; inverse pipelined on lanes 0-15 (cg==0).
// ---------------------------------------------------------------------------
__global__ void __launch_bounds__(256, 1)
k1_factor(int s, int parity)
{
    const int j   = s - 1 + 2 * s * blockIdx.x;
    const int tid = threadIdx.x;
    const int cg  = tid >> 4;
    const int rg  = tid & 15;
    const int c0  = 12 * cg;
    const int r0  = 4 * rg;

    const float* Aj = gA + j * BSZ;
    const float* Cj = gCb[parity] + j * BSZ;
    const float* Bj = gBb[parity] + j * BSZ;

    float m[4][12];
    float my[4];
    // load: 4-col chunks never straddle the 64-aligned regions (c0 % 4 == 0)
#pragma unroll
    for (int r = 0; r < 4; r++) {
        int row = r0 + r;
#pragma unroll
        for (int ch = 0; ch < 3; ch++) {
            int cc = c0 + 4 * ch;
            float4 v;
            if      (cc < 64)  v = *(const float4*)&Aj[row * BD + cc];
            else if (cc < 128) v = *(const float4*)&Cj[row * BD + (cc - 64)];
            else               v = *(const float4*)&Bj[row * BD + (cc - 128)];
            m[r][4 * ch] = v.x; m[r][4 * ch + 1] = v.y;
            m[r][4 * ch + 2] = v.z; m[r][4 * ch + 3] = v.w;
        }
        my[r] = (cg == 15) ? gy[j * BD + row] : 0.0f;
    }

    __shared__ float s_prow[2][4][200];   // pivot rows (raw), double buffered
    __shared__ float s_pcol[2][4][64];    // pivot cols, transposed [t][row]
    __shared__ float s_pblk[2][4][4];     // NEXT window 4x4 block (raw)
    __shared__ float s_W[2][16];          // P^{-1}, row-major [4r+t]

    // ---- prologue --------------------------------------------------------
    if (rg == 0) {                        // rows 0..3 -> pivot rows window 0
#pragma unroll
        for (int r = 0; r < 4; r++) {
            *(float4*)&s_prow[0][r][c0]     = make_float4(m[r][0], m[r][1], m[r][2],  m[r][3]);
            *(float4*)&s_prow[0][r][c0 + 4] = make_float4(m[r][4], m[r][5], m[r][6],  m[r][7]);
            *(float4*)&s_prow[0][r][c0 + 8] = make_float4(m[r][8], m[r][9], m[r][10], m[r][11]);
            if (cg == 15) s_prow[0][r][192] = my[r];
        }
    }
    if (cg == 0) {
#pragma unroll
        for (int r = 0; r < 4; r++)
#pragma unroll
            for (int t = 0; t < 4; t++) s_pcol[0][t][r0 + r] = m[r][t];
        if (rg == 1) {
#pragma unroll
            for (int r = 0; r < 4; r++)
#pragma unroll
                for (int t = 0; t < 4; t++) s_pblk[0][r][t] = m[r][4 + t];
        }
    }
    __syncthreads();
    if (tid < 16) {
        int r4 = tid >> 2, ccl = tid & 3;
        s_W[0][tid] = gj4_inverse_lane(s_pcol[0][ccl][r4], r4, ccl);
    }
    __syncthreads();

    // ---- 16 pipelined rank-4 iterations ----------------------------------
    for (int it = 0; it < 16; it++) {
        const int k  = 4 * it;
        const int b  = it & 1;
        const int nb = b ^ 1;
        const int kn = k + 4;
        const bool ispiv = (rg == it);
        const bool live  = (c0 + 11 >= kn) || (cg == 15);

        float4 W0 = *(const float4*)&s_W[b][0];
        float4 W1 = *(const float4*)&s_W[b][4];
        float4 W2 = *(const float4*)&s_W[b][8];
        float4 W3 = *(const float4*)&s_W[b][12];

        float u[4][4];
        if (live) {
#pragma unroll
            for (int r = 0; r < 4; r++) {
                if (ispiv) {
                    float4 Wr = (r == 0) ? W0 : (r == 1) ? W1 : (r == 2) ? W2 : W3;
                    u[r][0] = Wr.x; u[r][1] = Wr.y; u[r][2] = Wr.z; u[r][3] = Wr.w;
                } else {
                    float v0 = s_pcol[b][0][r0 + r];
                    float v1 = s_pcol[b][1][r0 + r];
                    float v2 = s_pcol[b][2][r0 + r];
                    float v3 = s_pcol[b][3][r0 + r];
                    u[r][0] = -(v0 * W0.x + v1 * W1.x + v2 * W2.x + v3 * W3.x);
                    u[r][1] = -(v0 * W0.y + v1 * W1.y + v2 * W2.y + v3 * W3.y);
                    u[r][2] = -(v0 * W0.z + v1 * W1.z + v2 * W2.z + v3 * W3.z);
                    u[r][3] = -(v0 * W0.w + v1 * W1.w + v2 * W2.w + v3 * W3.w);
                }
            }
#pragma unroll
            for (int ch = 0; ch < 3; ch++) {
                int cc = c0 + 4 * ch;
                if (cc + 3 >= kn) {
                    float4 p0 = *(const float4*)&s_prow[b][0][cc];
                    float4 p1 = *(const float4*)&s_prow[b][1][cc];
                    float4 p2 = *(const float4*)&s_prow[b][2][cc];
                    float4 p3 = *(const float4*)&s_prow[b][3][cc];
#pragma unroll
                    for (int r = 0; r < 4; r++) {
                        float b0 = ispiv ? 0.0f : m[r][4 * ch + 0];
                        float b1 = ispiv ? 0.0f : m[r][4 * ch + 1];
                        float b2 = ispiv ? 0.0f : m[r][4 * ch + 2];
                        float b3 = ispiv ? 0.0f : m[r][4 * ch + 3];
                        m[r][4 * ch + 0] = b0 + u[r][0] * p0.x + u[r][1] * p1.x + u[r][2] * p2.x + u[r][3] * p3.x;
                        m[r][4 * ch + 1] = b1 + u[r][0] * p0.y + u[r][1] * p1.y + u[r][2] * p2.y + u[r][3] * p3.y;
                        m[r][4 * ch + 2] = b2 + u[r][0] * p0.z + u[r][1] * p1.z + u[r][2] * p2.z + u[r][3] * p3.z;
                        m[r][4 * ch + 3] = b3 + u[r][0] * p0.w + u[r][1] * p1.w + u[r][2] * p2.w + u[r][3] * p3.w;
                    }
                }
            }
            if (cg == 15) {
                float py0 = s_prow[b][0][192], py1 = s_prow[b][1][192];
                float py2 = s_prow[b][2][192], py3 = s_prow[b][3][192];
#pragma unroll
                for (int r = 0; r < 4; r++) {
                    float bb = ispiv ? 0.0f : my[r];
                    my[r] = bb + u[r][0] * py0 + u[r][1] * py1 + u[r][2] * py2 + u[r][3] * py3;
                }
            }
        }

        if (it < 15) {
            // ---- concurrent next-window pivot inverse (lanes 0-15, cg==0)
            if (tid < 16) {
                int r4 = tid >> 2, ccl = tid & 3;
                float v0 = s_pcol[b][0][kn + r4];
                float v1 = s_pcol[b][1][kn + r4];
                float v2 = s_pcol[b][2][kn + r4];
                float v3 = s_pcol[b][3][kn + r4];
                float t0 = -(v0 * W0.x + v1 * W1.x + v2 * W2.x + v3 * W3.x);
                float t1 = -(v0 * W0.y + v1 * W1.y + v2 * W2.y + v3 * W3.y);
                float t2 = -(v0 * W0.z + v1 * W1.z + v2 * W2.z + v3 * W3.z);
                float t3 = -(v0 * W0.w + v1 * W1.w + v2 * W2.w + v3 * W3.w);
                float av = s_pblk[b][r4][ccl]
                         + t0 * s_prow[b][0][kn + ccl]
                         + t1 * s_prow[b][1][kn + ccl]
                         + t2 * s_prow[b][2][kn + ccl]
                         + t3 * s_prow[b][3][kn + ccl];
                s_W[nb][tid] = gj4_inverse_lane(av, r4, ccl);
            }
            // ---- publishes for window kn --------------------------------
            if (rg == it + 1 && live) {               // pivot rows (raw)
#pragma unroll
                for (int r = 0; r < 4; r++) {
                    *(float4*)&s_prow[nb][r][c0]     = make_float4(m[r][0], m[r][1], m[r][2],  m[r][3]);
                    *(float4*)&s_prow[nb][r][c0 + 4] = make_float4(m[r][4], m[r][5], m[r][6],  m[r][7]);
                    *(float4*)&s_prow[nb][r][c0 + 8] = make_float4(m[r][8], m[r][9], m[r][10], m[r][11]);
                    if (cg == 15) s_prow[nb][r][192] = my[r];
                }
            }
            if (cg == kn / 12) {                      // pivot cols
                int qoff = kn - 12 * (kn / 12);
#pragma unroll
                for (int r = 0; r < 4; r++)
#pragma unroll
                    for (int t = 0; t < 4; t++)
                        s_pcol[nb][t][r0 + r] = m[r][qoff + t];
            }
            if (it <= 13) {                           // block for window kn+4
                int k8 = k + 8;
                if (rg == it + 2 && cg == k8 / 12) {
                    int qoff2 = k8 - 12 * (k8 / 12);
#pragma unroll
                    for (int r = 0; r < 4; r++)
#pragma unroll
                        for (int t = 0; t < 4; t++)
                            s_pblk[nb][r][t] = m[r][qoff2 + t];
                }
            }
        }
        __syncthreads();
    }

    // ---- write Z = [ZC | ZB | Zy] ----------------------------------------
#pragma unroll
    for (int r = 0; r < 4; r++) {
        int row = r0 + r;
#pragma unroll
        for (int ch = 0; ch < 3; ch++) {
            int cc = c0 + 4 * ch;
            float4 v = make_float4(m[r][4 * ch], m[r][4 * ch + 1],
                                   m[r][4 * ch + 2], m[r][4 * ch + 3]);
            if      (cc >= 64 && cc < 128) *(float4*)&gZC[j * BSZ + row * BD + (cc - 64)]  = v;
            else if (cc >= 128)            *(float4*)&gZB[j * BSZ + row * BD + (cc - 128)] = v;
        }
        if (cg == 15) gZy[j * BD + row] = my[r];
    }
}

// ---------------------------------------------------------------------------
// K2: Schur updates (unchanged)
// ---------------------------------------------------------------------------
#define K2_SMEM (4 * 64 * 68 * 4)

__global__ void __launch_bounds__(256, 1)
k2_update(int s, int p)
{
    const int i    = 2 * s - 1 + 2 * s * blockIdx.x;
    const int task = blockIdx.y;
    const int jm   = i - s;
    const int jp   = (i + s > 63) ? 63 : (i + s);
    const int tid  = threadIdx.x;

    if (task == 3) {
        __shared__ float sy1[64], sy2[64];
        if (tid < 64) { sy1[tid] = gZy[jm * BD + tid]; sy2[tid] = gZy[jp * BD + tid]; }
        __syncthreads();
        if (tid < 64) {
            float acc = gy[i * BD + tid];
            const float* cp = gCb[p] + i * BSZ + tid * BD;
            const float* bp = gBb[p] + i * BSZ + tid * BD;
#pragma unroll 8
            for (int b = 0; b < 64; b++) acc -= cp[b] * sy1[b] + bp[b] * sy2[b];
            gy[i * BD + tid] = acc;
        }
        return;
    }

    extern __shared__ float sm2[];
    float* P1 = sm2;
    float* Q1 = sm2 + 64 * 68;
    float* P2 = sm2 + 2 * 64 * 68;
    float* Q2 = sm2 + 3 * 64 * 68;

    const float *p1g, *q1g, *p2g = nullptr, *q2g = nullptr;
    if (task == 0) {
        p1g = gCb[p] + i * BSZ;  q1g = gZB + jm * BSZ;
        p2g = gBb[p] + i * BSZ;  q2g = gZC + jp * BSZ;
    } else if (task == 1) {
        p1g = gCb[p] + i * BSZ;  q1g = gZC + jm * BSZ;
    } else {
        p1g = gBb[p] + i * BSZ;  q1g = gZB + jp * BSZ;
    }

    for (int e = tid; e < BSZ; e += 256) {
        int r = e >> 6, c = e & 63;
        P1[r * 68 + c] = p1g[e];
        Q1[r * 68 + c] = q1g[e];
        if (task == 0) { P2[r * 68 + c] = p2g[e]; Q2[r * 68 + c] = q2g[e]; }
    }
    __syncthreads();

    const int r0 = (tid >> 4) << 2;
    const int cc = (tid & 15) << 2;
    float acc[4][4];
#pragma unroll
    for (int u = 0; u < 4; u++)
#pragma unroll
        for (int v = 0; v < 4; v++) acc[u][v] = 0.0f;

    if (task == 0) {
        for (int k = 0; k < 64; k++) {
            float4 b1 = *(const float4*)&Q1[k * 68 + cc];
            float4 b2 = *(const float4*)&Q2[k * 68 + cc];
#pragma unroll
            for (int u = 0; u < 4; u++) {
                float a1 = P1[(r0 + u) * 68 + k];
                float a2 = P2[(r0 + u) * 68 + k];
                acc[u][0] += a1 * b1.x + a2 * b2.x;
                acc[u][1] += a1 * b1.y + a2 * b2.y;
                acc[u][2] += a1 * b1.z + a2 * b2.z;
                acc[u][3] += a1 * b1.w + a2 * b2.w;
            }
        }
        float* dst = gA + i * BSZ;
#pragma unroll
        for (int u = 0; u < 4; u++) {
            float4 o = *(float4*)&dst[(r0 + u) * BD + cc];
            o.x -= acc[u][0]; o.y -= acc[u][1]; o.z -= acc[u][2]; o.w -= acc[u][3];
            *(float4*)&dst[(r0 + u) * BD + cc] = o;
        }
    } else {
        for (int k = 0; k < 64; k++) {
            float4 b1 = *(const float4*)&Q1[k * 68 + cc];
#pragma unroll
            for (int u = 0; u < 4; u++) {
                float a1 = P1[(r0 + u) * 68 + k];
                acc[u][0] += a1 * b1.x;
                acc[u][1] += a1 * b1.y;
                acc[u][2] += a1 * b1.z;
                acc[u][3] += a1 * b1.w;
            }
        }
        float* dst = ((task == 1) ? gCb[p ^ 1] : gBb[p ^ 1]) + i * BSZ;
#pragma unroll
        for (int u = 0; u < 4; u++)
            *(float4*)&dst[(r0 + u) * BD + cc] =
                make_float4(-acc[u][0], -acc[u][1], -acc[u][2], -acc[u][3]);
    }
}

// ---------------------------------------------------------------------------
// Backsub (unchanged)
// ---------------------------------------------------------------------------
__global__ void __launch_bounds__(1024, 1)
backsub_kernel(float* __restrict__ out)
{
    __shared__ float sx[NBLK * BD];
    const int tid = threadIdx.x;
    for (int e = tid; e < NBLK * BD; e += 1024) sx[e] = 0.0f;
    __syncthreads();

    for (int lev = 7; lev >= 1; lev--) {
        int s  = 1 << (lev - 1);
        int ne = (lev == 7) ? 1 : (32 >> (lev - 1));
        for (int idx = tid; idx < ne * 64; idx += 1024) {
            int t = idx >> 6, a = idx & 63;
            int j = s - 1 + 2 * s * t;
            int jm = j - s; if (jm < 0)  jm = 0;
            int jp = j + s; if (jp > 63) jp = 63;
            const float4* zc = (const float4*)(gZC + j * BSZ + a * BD);
            const float4* zb = (const float4*)(gZB + j * BSZ + a * BD);
            float s0 = 0.f, s1 = 0.f, s2 = 0.f, s3 = 0.f;
#pragma unroll
            for (int w = 0; w < 16; w++) {
                float4 c4 = zc[w], b4 = zb[w];
                s0 += c4.x * sx[jm * BD + 4 * w]     + b4.x * sx[jp * BD + 4 * w];
                s1 += c4.y * sx[jm * BD + 4 * w + 1] + b4.y * sx[jp * BD + 4 * w + 1];
                s2 += c4.z * sx[jm * BD + 4 * w + 2] + b4.z * sx[jp * BD + 4 * w + 2];
                s3 += c4.w * sx[jm * BD + 4 * w + 3] + b4.w * sx[jp * BD + 4 * w + 3];
            }
            float acc = gZy[j * BD + a] - (s0 + s1 + s2 + s3);
            sx[j * BD + a]  = acc;
            out[j * BD + a] = acc;
        }
        __syncthreads();
    }
}

// ---------------------------------------------------------------------------
// kernel_launch
// ---------------------------------------------------------------------------
extern "C" void kernel_launch(void* const* d_in, const int* in_sizes, int n_in,
                              void* d_out, int out_size)
{
    const float* h    = (const float*)d_in[0];
    const float* phi  = (const float*)d_in[1];
    const float* base = (const float*)d_in[2];
    const float* over = (const float*)d_in[3];
    const float* melt = (const float*)d_in[4];
    const float* len  = (const float*)d_in[5];
    const int*   adj  = (const int*)  d_in[6];
    const int*   io   = (const int*)  d_in[7];
    float* out = (float*)d_out;

    static int once = []() {
        cudaFuncSetAttribute(k2_update,
                             cudaFuncAttributeMaxDynamicSharedMemorySize,
                             K2_SMEM);
        return 0;
    }();
    (void)once;

    assemble_kernel<<<32, 128>>>(h, phi, base, over, melt, len, adj, io);

    for (int lev = 1; lev <= 6; lev++) {
        int s = 1 << (lev - 1);
        int n = 32 >> (lev - 1);
        int p = (lev - 1) & 1;
        k1_factor<<<n, 256>>>(s, p);
        k2_update<<<dim3(n, 4), 256, K2_SMEM>>>(s, p);
    }
    k1_factor<<<1, 256>>>(64, 0);
    backsub_kernel<<<1, 1024>>>(out);
}

// round 8
// speedup vs baseline: 1.2997x; 1.1631x over previous
#include <cuda_runtime.h>
#include <cuda_bf16.h>

// SubglacialDrainageSystem: L x = f on a 64x64 grid.
// Block cyclic reduction over the 64-block tridiagonal structure (BD=64).
// R7: k1 = pipelined rank-4 in-place Gauss-Jordan INVERSION (live width 65,
// not 193): inverse columns replace eliminated A columns (sweep operator),
// window columns get the already-computed u vectors for free. ZC/ZB are formed
// in the epilogue: level 1 by diagonal column-scaling (C,B diagonal), levels
// >=2 by a fused in-CTA GEMM. Level-1 k2 degenerates to row scalings.

#define NBLK 64
#define BD   64
#define BSZ  (BD * BD)

static __device__ float gA [NBLK * BSZ];
static __device__ float gCb[2][NBLK * BSZ];
static __device__ float gBb[2][NBLK * BSZ];
static __device__ float gy [NBLK * BD];
static __device__ float gZC[NBLK * BSZ];
static __device__ float gZB[NBLK * BSZ];
static __device__ float gZy[NBLK * BD];

// ---------------------------------------------------------------------------
// Assembly
// ---------------------------------------------------------------------------
__global__ void assemble_kernel(const float* __restrict__ h,
                                const float* __restrict__ phi,
                                const float* __restrict__ base,
                                const float* __restrict__ over,
                                const float* __restrict__ melt,
                                const float* __restrict__ len,
                                const int*   __restrict__ adj,
                                const int*   __restrict__ io)
{
    int i = blockIdx.x * blockDim.x + threadIdx.x;
    if (i >= NBLK * BD) return;
    int r = i >> 6, a = i & 63;

    float4 z = make_float4(0.f, 0.f, 0.f, 0.f);
    float4* rowA = (float4*)(gA     + r * BSZ + a * BD);
    float4* rowC = (float4*)(gCb[0] + r * BSZ + a * BD);
    float4* rowB = (float4*)(gBb[0] + r * BSZ + a * BD);
#pragma unroll
    for (int b = 0; b < 16; b++) { rowA[b] = z; rowC[b] = z; rowB[b] = z; }

    const bool infl = (io[i] == 1);
    const double hi = (double)h[i];
    const double pi = (double)phi[i];
    double diag = 0.0;
    double cf0 = 0.0, cf1 = 0.0, cf2 = 0.0, cf3 = 0.0;

#pragma unroll
    for (int k = 0; k < 4; k++) {           // 0 north, 1 south, 2 west, 3 east
        int   j = adj[i * 4 + k];
        float L = len[i * 4 + k];
        double cc = 0.0;
        if (j >= 0 && L > 0.0f && !infl) {
            double hf   = 0.5 * (hi + (double)h[j]);
            double dphi = fabs(pi - (double)phi[j]);
            double g    = fmax(dphi, 1e-12) / (double)L;
            cc = -0.01 * pow(hf, 1.25) * (double)L * rsqrt(g);
            diag -= cc;
        }
        if (k == 0) cf0 = cc; else if (k == 1) cf1 = cc;
        else if (k == 2) cf2 = cc; else cf3 = cc;
    }

    gA[r * BSZ + a * BD + a] = infl ? 1.0f : (float)diag;
    if (a > 0)  gA[r * BSZ + a * BD + (a - 1)] = (float)cf2;
    if (a < 63) gA[r * BSZ + a * BD + (a + 1)] = (float)cf3;
    gCb[0][r * BSZ + a * BD + a] = (float)cf0;
    gBb[0][r * BSZ + a * BD + a] = (float)cf1;
    gy[i] = infl ? (float)((double)base[i] - (double)over[i]) : melt[i];
}

// ---------------------------------------------------------------------------
// 16-lane 4x4 Gauss-Jordan inverse (lanes 0-15 of warp 0; lane = r*4+c).
// ---------------------------------------------------------------------------
__device__ __forceinline__ float gj4_inverse_lane(float av, int r, int c)
{
    const unsigned am = 0xFFFFu;
    float iv = (r == c) ? 1.0f : 0.0f;
#pragma unroll
    for (int p = 0; p < 4; p++) {
        float app = __shfl_sync(am, av, p * 4 + p);
        float apc = __shfl_sync(am, av, p * 4 + c);
        float ipc = __shfl_sync(am, iv, p * 4 + c);
        float arp = __shfl_sync(am, av, r * 4 + p);
        float rinv = __fdividef(1.0f, app);
        if (r == p) { av = apc * rinv;          iv = ipc * rinv; }
        else        { float f = arp * rinv; av -= f * apc; iv -= f * ipc; }
    }
    return iv;
}

// ---------------------------------------------------------------------------
// K1: pipelined rank-4 in-place GJ inversion of [A | y] (width 65).
// 512 threads: rg = tid&31 owns rows {2rg, 2rg+1}; cg = tid>>5 owns cols
// [4cg, 4cg+4) (+y if cg==15). One __syncthreads per iteration; next-window
// 4x4 pivot inverse pipelined on lanes 0-15.
// mode 0: epilogue ZC/ZB by diagonal column scaling (level 1)
// mode 1: epilogue ZC/ZB by fused GEMM  Ainv * C, Ainv * B (levels 2-6)
// mode 2: epilogue Zy only (top block)
// ---------------------------------------------------------------------------
__global__ void __launch_bounds__(512, 1)
k1inv(int s, int parity, int mode)
{
    const int j   = s - 1 + 2 * s * blockIdx.x;
    const int tid = threadIdx.x;
    const int rg  = tid & 31;
    const int cg  = tid >> 5;
    const int c0  = 4 * cg;
    const int r0  = 2 * rg;

    const float* Aj = gA + j * BSZ;

    float m[2][4], my[2];
#pragma unroll
    for (int r = 0; r < 2; r++) {
        float4 v = *(const float4*)&Aj[(r0 + r) * BD + c0];
        m[r][0] = v.x; m[r][1] = v.y; m[r][2] = v.z; m[r][3] = v.w;
        my[r] = (cg == 15) ? gy[j * BD + r0 + r] : 0.0f;
    }

    __shared__ float s_prow[2][4][68];     // current pivot rows (full width)
    __shared__ float s_pcol[2][4][64];     // current pivot cols, [t][row]
    __shared__ float s_pblk[2][4][4];      // NEXT window 4x4 block (raw)
    __shared__ float s_W[2][16];           // P^{-1}, row-major [4r+t]
    __shared__ float s_Ai[64][68];         // Ainv staging for mode-1 GEMM

    // ---- prologue: window 0 --------------------------------------------
    if (rg < 2) {                          // rows 0..3
#pragma unroll
        for (int r = 0; r < 2; r++) {
            *(float4*)&s_prow[0][r0 + r][c0] =
                make_float4(m[r][0], m[r][1], m[r][2], m[r][3]);
            if (cg == 15) s_prow[0][r0 + r][64] = my[r];
        }
    }
    if (cg == 0) {
#pragma unroll
        for (int r = 0; r < 2; r++)
#pragma unroll
            for (int t = 0; t < 4; t++) s_pcol[0][t][r0 + r] = m[r][t];
    }
    if (cg == 1 && (rg >> 1) == 1) {       // rows 4..7, cols 4..7
#pragma unroll
        for (int r = 0; r < 2; r++)
#pragma unroll
            for (int t = 0; t < 4; t++) s_pblk[0][r0 + r - 4][t] = m[r][t];
    }
    __syncthreads();
    if (tid < 16)
        s_W[0][tid] = gj4_inverse_lane(s_pcol[0][tid & 3][tid >> 2],
                                       tid >> 2, tid & 3);
    __syncthreads();

    // ---- 16 pipelined rank-4 sweep iterations ---------------------------
    for (int it = 0; it < 16; it++) {
        const int b  = it & 1;
        const int nb = b ^ 1;
        const int kn = 4 * it + 4;
        const bool ispiv = ((rg >> 1) == it);

        float4 W0 = *(const float4*)&s_W[b][0];
        float4 W1 = *(const float4*)&s_W[b][4];
        float4 W2 = *(const float4*)&s_W[b][8];
        float4 W3 = *(const float4*)&s_W[b][12];

        float u[2][4];
        if (ispiv) {
            bool hi = (rg & 1);
            float4 wa = hi ? W2 : W0;      // local pivot row 2*hi
            float4 wb = hi ? W3 : W1;      // local pivot row 2*hi+1
            u[0][0] = wa.x; u[0][1] = wa.y; u[0][2] = wa.z; u[0][3] = wa.w;
            u[1][0] = wb.x; u[1][1] = wb.y; u[1][2] = wb.z; u[1][3] = wb.w;
        } else {
#pragma unroll
            for (int r = 0; r < 2; r++) {
                float v0 = s_pcol[b][0][r0 + r];
                float v1 = s_pcol[b][1][r0 + r];
                float v2 = s_pcol[b][2][r0 + r];
                float v3 = s_pcol[b][3][r0 + r];
                u[r][0] = -(v0 * W0.x + v1 * W1.x + v2 * W2.x + v3 * W3.x);
                u[r][1] = -(v0 * W0.y + v1 * W1.y + v2 * W2.y + v3 * W3.y);
                u[r][2] = -(v0 * W0.z + v1 * W1.z + v2 * W2.z + v3 * W3.z);
                u[r][3] = -(v0 * W0.w + v1 * W1.w + v2 * W2.w + v3 * W3.w);
            }
        }

        if (cg == it) {
            // window columns: Q <- -Q P^{-1} = u (non-pivot); P <- W (pivot)
#pragma unroll
            for (int r = 0; r < 2; r++)
#pragma unroll
                for (int t = 0; t < 4; t++) m[r][t] = u[r][t];
        } else {
            float4 p0 = *(const float4*)&s_prow[b][0][c0];
            float4 p1 = *(const float4*)&s_prow[b][1][c0];
            float4 p2 = *(const float4*)&s_prow[b][2][c0];
            float4 p3 = *(const float4*)&s_prow[b][3][c0];
#pragma unroll
            for (int r = 0; r < 2; r++) {
                float b0 = ispiv ? 0.0f : m[r][0];
                float b1 = ispiv ? 0.0f : m[r][1];
                float b2 = ispiv ? 0.0f : m[r][2];
                float b3 = ispiv ? 0.0f : m[r][3];
                m[r][0] = b0 + u[r][0] * p0.x + u[r][1] * p1.x + u[r][2] * p2.x + u[r][3] * p3.x;
                m[r][1] = b1 + u[r][0] * p0.y + u[r][1] * p1.y + u[r][2] * p2.y + u[r][3] * p3.y;
                m[r][2] = b2 + u[r][0] * p0.z + u[r][1] * p1.z + u[r][2] * p2.z + u[r][3] * p3.z;
                m[r][3] = b3 + u[r][0] * p0.w + u[r][1] * p1.w + u[r][2] * p2.w + u[r][3] * p3.w;
            }
        }
        if (cg == 15) {
            float py0 = s_prow[b][0][64], py1 = s_prow[b][1][64];
            float py2 = s_prow[b][2][64], py3 = s_prow[b][3][64];
#pragma unroll
            for (int r = 0; r < 2; r++) {
                float bb = ispiv ? 0.0f : my[r];
                my[r] = bb + u[r][0] * py0 + u[r][1] * py1 + u[r][2] * py2 + u[r][3] * py3;
            }
        }

        if (it < 15) {
            // pipelined next-window pivot-block inverse (lanes 0-15)
            if (tid < 16) {
                int r4 = tid >> 2, ccl = tid & 3;
                float v0 = s_pcol[b][0][kn + r4];
                float v1 = s_pcol[b][1][kn + r4];
                float v2 = s_pcol[b][2][kn + r4];
                float v3 = s_pcol[b][3][kn + r4];
                float t0 = -(v0 * W0.x + v1 * W1.x + v2 * W2.x + v3 * W3.x);
                float t1 = -(v0 * W0.y + v1 * W1.y + v2 * W2.y + v3 * W3.y);
                float t2 = -(v0 * W0.z + v1 * W1.z + v2 * W2.z + v3 * W3.z);
                float t3 = -(v0 * W0.w + v1 * W1.w + v2 * W2.w + v3 * W3.w);
                float av = s_pblk[b][r4][ccl]
                         + t0 * s_prow[b][0][kn + ccl]
                         + t1 * s_prow[b][1][kn + ccl]
                         + t2 * s_prow[b][2][kn + ccl]
                         + t3 * s_prow[b][3][kn + ccl];
                s_W[nb][tid] = gj4_inverse_lane(av, r4, ccl);
            }
            if ((rg >> 1) == it + 1) {     // next pivot rows
#pragma unroll
                for (int r = 0; r < 2; r++) {
                    *(float4*)&s_prow[nb][r0 + r - kn][c0] =
                        make_float4(m[r][0], m[r][1], m[r][2], m[r][3]);
                    if (cg == 15) s_prow[nb][r0 + r - kn][64] = my[r];
                }
            }
            if (cg == it + 1) {            // next pivot cols
#pragma unroll
                for (int r = 0; r < 2; r++)
#pragma unroll
                    for (int t = 0; t < 4; t++) s_pcol[nb][t][r0 + r] = m[r][t];
            }
            if (it <= 13 && cg == it + 2 && (rg >> 1) == it + 2) {
#pragma unroll
                for (int r = 0; r < 2; r++)
#pragma unroll
                    for (int t = 0; t < 4; t++)
                        s_pblk[nb][r0 + r - (kn + 4)][t] = m[r][t];
            }
        }
        __syncthreads();
    }

    // ---- epilogue --------------------------------------------------------
    if (cg == 15) {
        gZy[j * BD + r0]     = my[0];
        gZy[j * BD + r0 + 1] = my[1];
    }

    if (mode == 0) {
        // level 1: C, B diagonal -> ZC = Ainv * diag(c), ZB = Ainv * diag(b)
        const float* Cj = gCb[0] + j * BSZ;
        const float* Bj = gBb[0] + j * BSZ;
        float cd[4], bd[4];
#pragma unroll
        for (int t = 0; t < 4; t++) {
            cd[t] = Cj[(c0 + t) * 65];     // diagonal entry, col c0+t
            bd[t] = Bj[(c0 + t) * 65];
        }
#pragma unroll
        for (int r = 0; r < 2; r++) {
            *(float4*)&gZC[j * BSZ + (r0 + r) * BD + c0] =
                make_float4(m[r][0] * cd[0], m[r][1] * cd[1],
                            m[r][2] * cd[2], m[r][3] * cd[3]);
            *(float4*)&gZB[j * BSZ + (r0 + r) * BD + c0] =
                make_float4(m[r][0] * bd[0], m[r][1] * bd[1],
                            m[r][2] * bd[2], m[r][3] * bd[3]);
        }
    } else if (mode == 1) {
        // levels 2-6: fused GEMM ZC = Ainv*C, ZB = Ainv*B
#pragma unroll
        for (int r = 0; r < 2; r++)
            *(float4*)&s_Ai[r0 + r][c0] =
                make_float4(m[r][0], m[r][1], m[r][2], m[r][3]);
        __syncthreads();
        const float* Cj = gCb[parity] + j * BSZ;
        const float* Bj = gBb[parity] + j * BSZ;
        float4 zc0 = make_float4(0,0,0,0), zc1 = zc0, zb0 = zc0, zb1 = zc0;
#pragma unroll 4
        for (int k4 = 0; k4 < 16; k4++) {
            float4 a0 = *(const float4*)&s_Ai[r0][4 * k4];
            float4 a1 = *(const float4*)&s_Ai[r0 + 1][4 * k4];
            float a0a[4] = {a0.x, a0.y, a0.z, a0.w};
            float a1a[4] = {a1.x, a1.y, a1.z, a1.w};
#pragma unroll
            for (int kk = 0; kk < 4; kk++) {
                int k = 4 * k4 + kk;
                float4 cv = __ldg((const float4*)&Cj[k * BD + c0]);
                float4 bv = __ldg((const float4*)&Bj[k * BD + c0]);
                zc0.x += a0a[kk] * cv.x; zc0.y += a0a[kk] * cv.y;
                zc0.z += a0a[kk] * cv.z; zc0.w += a0a[kk] * cv.w;
                zc1.x += a1a[kk] * cv.x; zc1.y += a1a[kk] * cv.y;
                zc1.z += a1a[kk] * cv.z; zc1.w += a1a[kk] * cv.w;
                zb0.x += a0a[kk] * bv.x; zb0.y += a0a[kk] * bv.y;
                zb0.z += a0a[kk] * bv.z; zb0.w += a0a[kk] * bv.w;
                zb1.x += a1a[kk] * bv.x; zb1.y += a1a[kk] * bv.y;
                zb1.z += a1a[kk] * bv.z; zb1.w += a1a[kk] * bv.w;
            }
        }
        *(float4*)&gZC[j * BSZ + r0 * BD + c0]       = zc0;
        *(float4*)&gZC[j * BSZ + (r0 + 1) * BD + c0] = zc1;
        *(float4*)&gZB[j * BSZ + r0 * BD + c0]       = zb0;
        *(float4*)&gZB[j * BSZ + (r0 + 1) * BD + c0] = zb1;
    }
    // mode 2: Zy only
}

// ---------------------------------------------------------------------------
// K2 level 1: C_i, B_i diagonal -> all Schur updates are row scalings.
// One CTA per surviving (odd) block.
// ---------------------------------------------------------------------------
__global__ void __launch_bounds__(256, 1)
k2_lvl1()
{
    const int i   = 1 + 2 * blockIdx.x;
    const int jm  = i - 1;
    const int jp  = (i + 1 > 63) ? 63 : (i + 1);
    const int tid = threadIdx.x;

    __shared__ float scd[64], sbd[64];
    if (tid < 64) {
        scd[tid] = gCb[0][i * BSZ + tid * 65];
        sbd[tid] = gBb[0][i * BSZ + tid * 65];
    }
    __syncthreads();

    for (int e = tid; e < 1024; e += 256) {
        int r  = e >> 4;
        int c4 = (e & 15) << 2;
        float cdr = scd[r], bdr = sbd[r];
        int off = r * BD + c4;

        float4 zbm = *(const float4*)&gZB[jm * BSZ + off];
        float4 zcp = *(const float4*)&gZC[jp * BSZ + off];
        float4 a   = *(const float4*)&gA [i * BSZ + off];
        a.x -= cdr * zbm.x + bdr * zcp.x;
        a.y -= cdr * zbm.y + bdr * zcp.y;
        a.z -= cdr * zbm.z + bdr * zcp.z;
        a.w -= cdr * zbm.w + bdr * zcp.w;
        *(float4*)&gA[i * BSZ + off] = a;

        float4 zcm = *(const float4*)&gZC[jm * BSZ + off];
        *(float4*)&gCb[1][i * BSZ + off] =
            make_float4(-cdr * zcm.x, -cdr * zcm.y, -cdr * zcm.z, -cdr * zcm.w);
        float4 zbp = *(const float4*)&gZB[jp * BSZ + off];
        *(float4*)&gBb[1][i * BSZ + off] =
            make_float4(-bdr * zbp.x, -bdr * zbp.y, -bdr * zbp.z, -bdr * zbp.w);
    }
    if (tid < 64)
        gy[i * BD + tid] -= scd[tid] * gZy[jm * BD + tid]
                          + sbd[tid] * gZy[jp * BD + tid];
}

// ---------------------------------------------------------------------------
// K2 (levels >= 2): Schur updates via 64^3 GEMMs (unchanged from R6)
// ---------------------------------------------------------------------------
#define K2_SMEM (4 * 64 * 68 * 4)

__global__ void __launch_bounds__(256, 1)
k2_update(int s, int p)
{
    const int i    = 2 * s - 1 + 2 * s * blockIdx.x;
    const int task = blockIdx.y;
    const int jm   = i - s;
    const int jp   = (i + s > 63) ? 63 : (i + s);
    const int tid  = threadIdx.x;

    if (task == 3) {
        __shared__ float sy1[64], sy2[64];
        if (tid < 64) { sy1[tid] = gZy[jm * BD + tid]; sy2[tid] = gZy[jp * BD + tid]; }
        __syncthreads();
        if (tid < 64) {
            float acc = gy[i * BD + tid];
            const float* cp = gCb[p] + i * BSZ + tid * BD;
            const float* bp = gBb[p] + i * BSZ + tid * BD;
#pragma unroll 8
            for (int b = 0; b < 64; b++) acc -= cp[b] * sy1[b] + bp[b] * sy2[b];
            gy[i * BD + tid] = acc;
        }
        return;
    }

    extern __shared__ float sm2[];
    float* P1 = sm2;
    float* Q1 = sm2 + 64 * 68;
    float* P2 = sm2 + 2 * 64 * 68;
    float* Q2 = sm2 + 3 * 64 * 68;

    const float *p1g, *q1g, *p2g = nullptr, *q2g = nullptr;
    if (task == 0) {
        p1g = gCb[p] + i * BSZ;  q1g = gZB + jm * BSZ;
        p2g = gBb[p] + i * BSZ;  q2g = gZC + jp * BSZ;
    } else if (task == 1) {
        p1g = gCb[p] + i * BSZ;  q1g = gZC + jm * BSZ;
    } else {
        p1g = gBb[p] + i * BSZ;  q1g = gZB + jp * BSZ;
    }

    for (int e = tid; e < BSZ; e += 256) {
        int r = e >> 6, c = e & 63;
        P1[r * 68 + c] = p1g[e];
        Q1[r * 68 + c] = q1g[e];
        if (task == 0) { P2[r * 68 + c] = p2g[e]; Q2[r * 68 + c] = q2g[e]; }
    }
    __syncthreads();

    const int r0 = (tid >> 4) << 2;
    const int cc = (tid & 15) << 2;
    float acc[4][4];
#pragma unroll
    for (int u = 0; u < 4; u++)
#pragma unroll
        for (int v = 0; v < 4; v++) acc[u][v] = 0.0f;

    if (task == 0) {
        for (int k = 0; k < 64; k++) {
            float4 b1 = *(const float4*)&Q1[k * 68 + cc];
            float4 b2 = *(const float4*)&Q2[k * 68 + cc];
#pragma unroll
            for (int u = 0; u < 4; u++) {
                float a1 = P1[(r0 + u) * 68 + k];
                float a2 = P2[(r0 + u) * 68 + k];
                acc[u][0] += a1 * b1.x + a2 * b2.x;
                acc[u][1] += a1 * b1.y + a2 * b2.y;
                acc[u][2] += a1 * b1.z + a2 * b2.z;
                acc[u][3] += a1 * b1.w + a2 * b2.w;
            }
        }
        float* dst = gA + i * BSZ;
#pragma unroll
        for (int u = 0; u < 4; u++) {
            float4 o = *(float4*)&dst[(r0 + u) * BD + cc];
            o.x -= acc[u][0]; o.y -= acc[u][1]; o.z -= acc[u][2]; o.w -= acc[u][3];
            *(float4*)&dst[(r0 + u) * BD + cc] = o;
        }
    } else {
        for (int k = 0; k < 64; k++) {
            float4 b1 = *(const float4*)&Q1[k * 68 + cc];
#pragma unroll
            for (int u = 0; u < 4; u++) {
                float a1 = P1[(r0 + u) * 68 + k];
                acc[u][0] += a1 * b1.x;
                acc[u][1] += a1 * b1.y;
                acc[u][2] += a1 * b1.z;
                acc[u][3] += a1 * b1.w;
            }
        }
        float* dst = ((task == 1) ? gCb[p ^ 1] : gBb[p ^ 1]) + i * BSZ;
#pragma unroll
        for (int u = 0; u < 4; u++)
            *(float4*)&dst[(r0 + u) * BD + cc] =
                make_float4(-acc[u][0], -acc[u][1], -acc[u][2], -acc[u][3]);
    }
}

// ---------------------------------------------------------------------------
// Backsub (unchanged)
// ---------------------------------------------------------------------------
__global__ void __launch_bounds__(1024, 1)
backsub_kernel(float* __restrict__ out)
{
    __shared__ float sx[NBLK * BD];
    const int tid = threadIdx.x;
    for (int e = tid; e < NBLK * BD; e += 1024) sx[e] = 0.0f;
    __syncthreads();

    for (int lev = 7; lev >= 1; lev--) {
        int s  = 1 << (lev - 1);
        int ne = (lev == 7) ? 1 : (32 >> (lev - 1));
        for (int idx = tid; idx < ne * 64; idx += 1024) {
            int t = idx >> 6, a = idx & 63;
            int j = s - 1 + 2 * s * t;
            int jm = j - s; if (jm < 0)  jm = 0;
            int jp = j + s; if (jp > 63) jp = 63;
            const float4* zc = (const float4*)(gZC + j * BSZ + a * BD);
            const float4* zb = (const float4*)(gZB + j * BSZ + a * BD);
            float s0 = 0.f, s1 = 0.f, s2 = 0.f, s3 = 0.f;
#pragma unroll
            for (int w = 0; w < 16; w++) {
                float4 c4 = zc[w], b4 = zb[w];
                s0 += c4.x * sx[jm * BD + 4 * w]     + b4.x * sx[jp * BD + 4 * w];
                s1 += c4.y * sx[jm * BD + 4 * w + 1] + b4.y * sx[jp * BD + 4 * w + 1];
                s2 += c4.z * sx[jm * BD + 4 * w + 2] + b4.z * sx[jp * BD + 4 * w + 2];
                s3 += c4.w * sx[jm * BD + 4 * w + 3] + b4.w * sx[jp * BD + 4 * w + 3];
            }
            float acc = gZy[j * BD + a] - (s0 + s1 + s2 + s3);
            sx[j * BD + a]  = acc;
            out[j * BD + a] = acc;
        }
        __syncthreads();
    }
}

// ---------------------------------------------------------------------------
// kernel_launch
// ---------------------------------------------------------------------------
extern "C" void kernel_launch(void* const* d_in, const int* in_sizes, int n_in,
                              void* d_out, int out_size)
{
    const float* h    = (const float*)d_in[0];
    const float* phi  = (const float*)d_in[1];
    const float* base = (const float*)d_in[2];
    const float* over = (const float*)d_in[3];
    const float* melt = (const float*)d_in[4];
    const float* len  = (const float*)d_in[5];
    const int*   adj  = (const int*)  d_in[6];
    const int*   io   = (const int*)  d_in[7];
    float* out = (float*)d_out;

    static int once = []() {
        cudaFuncSetAttribute(k2_update,
                             cudaFuncAttributeMaxDynamicSharedMemorySize,
                             K2_SMEM);
        return 0;
    }();
    (void)once;

    assemble_kernel<<<32, 128>>>(h, phi, base, over, melt, len, adj, io);

    // level 1: eliminate even blocks; diagonal C/B specializations
    k1inv<<<32, 512>>>(1, 0, /*mode=*/0);
    k2_lvl1<<<32, 256>>>();

    // levels 2..6
    for (int lev = 2; lev <= 6; lev++) {
        int s = 1 << (lev - 1);
        int n = 32 >> (lev - 1);
        int p = (lev - 1) & 1;
        k1inv<<<n, 512>>>(s, p, /*mode=*/1);
        k2_update<<<dim3(n, 4), 256, K2_SMEM>>>(s, p);
    }

    // top block (j = 63): only Zy needed
    k1inv<<<1, 512>>>(64, 0, /*mode=*/2);
    backsub_kernel<<<1, 1024>>>(out);
}

// round 9
// speedup vs baseline: 1.3284x; 1.0221x over previous
#include <cuda_runtime.h>
#include <cuda_bf16.h>

// SubglacialDrainageSystem: L x = f on a 64x64 grid.
// Block cyclic reduction over the 64-block tridiagonal structure (BD=64).
// R9: k1inv = pure pipelined rank-4 in-place GJ inversion (writes Ainv);
// Z-formation moved to a parallel kZ kernel (grid n x 2); k2 rebalanced to
// 5 equal tasks (A update split into column halves). Level-1 keeps the
// diagonal C/B specializations.

#define NBLK 64
#define BD   64
#define BSZ  (BD * BD)

static __device__ float gA [NBLK * BSZ];
static __device__ float gAi[NBLK * BSZ];
static __device__ float gCb[2][NBLK * BSZ];
static __device__ float gBb[2][NBLK * BSZ];
static __device__ float gy [NBLK * BD];
static __device__ float gZC[NBLK * BSZ];
static __device__ float gZB[NBLK * BSZ];
static __device__ float gZy[NBLK * BD];

// ---------------------------------------------------------------------------
// Assembly
// ---------------------------------------------------------------------------
__global__ void assemble_kernel(const float* __restrict__ h,
                                const float* __restrict__ phi,
                                const float* __restrict__ base,
                                const float* __restrict__ over,
                                const float* __restrict__ melt,
                                const float* __restrict__ len,
                                const int*   __restrict__ adj,
                                const int*   __restrict__ io)
{
    int i = blockIdx.x * blockDim.x + threadIdx.x;
    if (i >= NBLK * BD) return;
    int r = i >> 6, a = i & 63;

    float4 z = make_float4(0.f, 0.f, 0.f, 0.f);
    float4* rowA = (float4*)(gA     + r * BSZ + a * BD);
    float4* rowC = (float4*)(gCb[0] + r * BSZ + a * BD);
    float4* rowB = (float4*)(gBb[0] + r * BSZ + a * BD);
#pragma unroll
    for (int b = 0; b < 16; b++) { rowA[b] = z; rowC[b] = z; rowB[b] = z; }

    const bool infl = (io[i] == 1);
    const double hi = (double)h[i];
    const double pi = (double)phi[i];
    double diag = 0.0;
    double cf0 = 0.0, cf1 = 0.0, cf2 = 0.0, cf3 = 0.0;

#pragma unroll
    for (int k = 0; k < 4; k++) {           // 0 north, 1 south, 2 west, 3 east
        int   j = adj[i * 4 + k];
        float L = len[i * 4 + k];
        double cc = 0.0;
        if (j >= 0 && L > 0.0f && !infl) {
            double hf   = 0.5 * (hi + (double)h[j]);
            double dphi = fabs(pi - (double)phi[j]);
            double g    = fmax(dphi, 1e-12) / (double)L;
            cc = -0.01 * pow(hf, 1.25) * (double)L * rsqrt(g);
            diag -= cc;
        }
        if (k == 0) cf0 = cc; else if (k == 1) cf1 = cc;
        else if (k == 2) cf2 = cc; else cf3 = cc;
    }

    gA[r * BSZ + a * BD + a] = infl ? 1.0f : (float)diag;
    if (a > 0)  gA[r * BSZ + a * BD + (a - 1)] = (float)cf2;
    if (a < 63) gA[r * BSZ + a * BD + (a + 1)] = (float)cf3;
    gCb[0][r * BSZ + a * BD + a] = (float)cf0;
    gBb[0][r * BSZ + a * BD + a] = (float)cf1;
    gy[i] = infl ? (float)((double)base[i] - (double)over[i]) : melt[i];
}

// ---------------------------------------------------------------------------
// 16-lane 4x4 Gauss-Jordan inverse (lanes 0-15 of warp 0; lane = r*4+c).
// ---------------------------------------------------------------------------
__device__ __forceinline__ float gj4_inverse_lane(float av, int r, int c)
{
    const unsigned am = 0xFFFFu;
    float iv = (r == c) ? 1.0f : 0.0f;
#pragma unroll
    for (int p = 0; p < 4; p++) {
        float app = __shfl_sync(am, av, p * 4 + p);
        float apc = __shfl_sync(am, av, p * 4 + c);
        float ipc = __shfl_sync(am, iv, p * 4 + c);
        float arp = __shfl_sync(am, av, r * 4 + p);
        float rinv = __fdividef(1.0f, app);
        if (r == p) { av = apc * rinv;          iv = ipc * rinv; }
        else        { float f = arp * rinv; av -= f * apc; iv -= f * ipc; }
    }
    return iv;
}

// ---------------------------------------------------------------------------
// K1: pipelined rank-4 in-place GJ inversion of [A | y] (width 65).
// 512 threads: rg = tid&31 owns rows {2rg, 2rg+1}; cg = tid>>5 owns cols
// [4cg, 4cg+4) (+y if cg==15). One __syncthreads per iteration; next-window
// 4x4 pivot inverse pipelined on lanes 0-15.
// mode 0: epilogue ZC/ZB by diagonal column scaling (level 1)
// mode 1: epilogue writes Ainv to gAi (kZ forms ZC/ZB)
// mode 2: epilogue Zy only (top block)
// ---------------------------------------------------------------------------
__global__ void __launch_bounds__(512, 1)
k1inv(int s, int mode)
{
    const int j   = s - 1 + 2 * s * blockIdx.x;
    const int tid = threadIdx.x;
    const int rg  = tid & 31;
    const int cg  = tid >> 5;
    const int c0  = 4 * cg;
    const int r0  = 2 * rg;

    const float* Aj = gA + j * BSZ;

    float m[2][4], my[2];
#pragma unroll
    for (int r = 0; r < 2; r++) {
        float4 v = *(const float4*)&Aj[(r0 + r) * BD + c0];
        m[r][0] = v.x; m[r][1] = v.y; m[r][2] = v.z; m[r][3] = v.w;
        my[r] = (cg == 15) ? gy[j * BD + r0 + r] : 0.0f;
    }

    __shared__ float s_prow[2][4][68];     // current pivot rows (full width)
    __shared__ float s_pcol[2][4][64];     // current pivot cols, [t][row]
    __shared__ float s_pblk[2][4][4];      // NEXT window 4x4 block (raw)
    __shared__ float s_W[2][16];           // P^{-1}, row-major [4r+t]

    // ---- prologue: window 0 --------------------------------------------
    if (rg < 2) {                          // rows 0..3
#pragma unroll
        for (int r = 0; r < 2; r++) {
            *(float4*)&s_prow[0][r0 + r][c0] =
                make_float4(m[r][0], m[r][1], m[r][2], m[r][3]);
            if (cg == 15) s_prow[0][r0 + r][64] = my[r];
        }
    }
    if (cg == 0) {
#pragma unroll
        for (int r = 0; r < 2; r++)
#pragma unroll
            for (int t = 0; t < 4; t++) s_pcol[0][t][r0 + r] = m[r][t];
    }
    if (cg == 1 && (rg >> 1) == 1) {       // rows 4..7, cols 4..7
#pragma unroll
        for (int r = 0; r < 2; r++)
#pragma unroll
            for (int t = 0; t < 4; t++) s_pblk[0][r0 + r - 4][t] = m[r][t];
    }
    __syncthreads();
    if (tid < 16)
        s_W[0][tid] = gj4_inverse_lane(s_pcol[0][tid & 3][tid >> 2],
                                       tid >> 2, tid & 3);
    __syncthreads();

    // ---- 16 pipelined rank-4 sweep iterations ---------------------------
    for (int it = 0; it < 16; it++) {
        const int b  = it & 1;
        const int nb = b ^ 1;
        const int kn = 4 * it + 4;
        const bool ispiv = ((rg >> 1) == it);

        float4 W0 = *(const float4*)&s_W[b][0];
        float4 W1 = *(const float4*)&s_W[b][4];
        float4 W2 = *(const float4*)&s_W[b][8];
        float4 W3 = *(const float4*)&s_W[b][12];

        float u[2][4];
        if (ispiv) {
            bool hi = (rg & 1);
            float4 wa = hi ? W2 : W0;      // local pivot row 2*hi
            float4 wb = hi ? W3 : W1;      // local pivot row 2*hi+1
            u[0][0] = wa.x; u[0][1] = wa.y; u[0][2] = wa.z; u[0][3] = wa.w;
            u[1][0] = wb.x; u[1][1] = wb.y; u[1][2] = wb.z; u[1][3] = wb.w;
        } else {
#pragma unroll
            for (int r = 0; r < 2; r++) {
                float v0 = s_pcol[b][0][r0 + r];
                float v1 = s_pcol[b][1][r0 + r];
                float v2 = s_pcol[b][2][r0 + r];
                float v3 = s_pcol[b][3][r0 + r];
                u[r][0] = -(v0 * W0.x + v1 * W1.x + v2 * W2.x + v3 * W3.x);
                u[r][1] = -(v0 * W0.y + v1 * W1.y + v2 * W2.y + v3 * W3.y);
                u[r][2] = -(v0 * W0.z + v1 * W1.z + v2 * W2.z + v3 * W3.z);
                u[r][3] = -(v0 * W0.w + v1 * W1.w + v2 * W2.w + v3 * W3.w);
            }
        }

        if (cg == it) {
            // window columns: Q <- -Q P^{-1} = u (non-pivot); P <- W (pivot)
#pragma unroll
            for (int r = 0; r < 2; r++)
#pragma unroll
                for (int t = 0; t < 4; t++) m[r][t] = u[r][t];
        } else {
            float4 p0 = *(const float4*)&s_prow[b][0][c0];
            float4 p1 = *(const float4*)&s_prow[b][1][c0];
            float4 p2 = *(const float4*)&s_prow[b][2][c0];
            float4 p3 = *(const float4*)&s_prow[b][3][c0];
#pragma unroll
            for (int r = 0; r < 2; r++) {
                float b0 = ispiv ? 0.0f : m[r][0];
                float b1 = ispiv ? 0.0f : m[r][1];
                float b2 = ispiv ? 0.0f : m[r][2];
                float b3 = ispiv ? 0.0f : m[r][3];
                m[r][0] = b0 + u[r][0] * p0.x + u[r][1] * p1.x + u[r][2] * p2.x + u[r][3] * p3.x;
                m[r][1] = b1 + u[r][0] * p0.y + u[r][1] * p1.y + u[r][2] * p2.y + u[r][3] * p3.y;
                m[r][2] = b2 + u[r][0] * p0.z + u[r][1] * p1.z + u[r][2] * p2.z + u[r][3] * p3.z;
                m[r][3] = b3 + u[r][0] * p0.w + u[r][1] * p1.w + u[r][2] * p2.w + u[r][3] * p3.w;
            }
        }
        if (cg == 15) {
            float py0 = s_prow[b][0][64], py1 = s_prow[b][1][64];
            float py2 = s_prow[b][2][64], py3 = s_prow[b][3][64];
#pragma unroll
            for (int r = 0; r < 2; r++) {
                float bb = ispiv ? 0.0f : my[r];
                my[r] = bb + u[r][0] * py0 + u[r][1] * py1 + u[r][2] * py2 + u[r][3] * py3;
            }
        }

        if (it < 15) {
            // pipelined next-window pivot-block inverse (lanes 0-15)
            if (tid < 16) {
                int r4 = tid >> 2, ccl = tid & 3;
                float v0 = s_pcol[b][0][kn + r4];
                float v1 = s_pcol[b][1][kn + r4];
                float v2 = s_pcol[b][2][kn + r4];
                float v3 = s_pcol[b][3][kn + r4];
                float t0 = -(v0 * W0.x + v1 * W1.x + v2 * W2.x + v3 * W3.x);
                float t1 = -(v0 * W0.y + v1 * W1.y + v2 * W2.y + v3 * W3.y);
                float t2 = -(v0 * W0.z + v1 * W1.z + v2 * W2.z + v3 * W3.z);
                float t3 = -(v0 * W0.w + v1 * W1.w + v2 * W2.w + v3 * W3.w);
                float av = s_pblk[b][r4][ccl]
                         + t0 * s_prow[b][0][kn + ccl]
                         + t1 * s_prow[b][1][kn + ccl]
                         + t2 * s_prow[b][2][kn + ccl]
                         + t3 * s_prow[b][3][kn + ccl];
                s_W[nb][tid] = gj4_inverse_lane(av, r4, ccl);
            }
            if ((rg >> 1) == it + 1) {     // next pivot rows
#pragma unroll
                for (int r = 0; r < 2; r++) {
                    *(float4*)&s_prow[nb][r0 + r - kn][c0] =
                        make_float4(m[r][0], m[r][1], m[r][2], m[r][3]);
                    if (cg == 15) s_prow[nb][r0 + r - kn][64] = my[r];
                }
            }
            if (cg == it + 1) {            // next pivot cols
#pragma unroll
                for (int r = 0; r < 2; r++)
#pragma unroll
                    for (int t = 0; t < 4; t++) s_pcol[nb][t][r0 + r] = m[r][t];
            }
            if (it <= 13 && cg == it + 2 && (rg >> 1) == it + 2) {
#pragma unroll
                for (int r = 0; r < 2; r++)
#pragma unroll
                    for (int t = 0; t < 4; t++)
                        s_pblk[nb][r0 + r - (kn + 4)][t] = m[r][t];
            }
        }
        __syncthreads();
    }

    // ---- epilogue --------------------------------------------------------
    if (cg == 15) {
        gZy[j * BD + r0]     = my[0];
        gZy[j * BD + r0 + 1] = my[1];
    }

    if (mode == 0) {
        // level 1: C, B diagonal -> ZC = Ainv * diag(c), ZB = Ainv * diag(b)
        const float* Cj = gCb[0] + j * BSZ;
        const float* Bj = gBb[0] + j * BSZ;
        float cd[4], bd[4];
#pragma unroll
        for (int t = 0; t < 4; t++) {
            cd[t] = Cj[(c0 + t) * 65];     // diagonal entry, col c0+t
            bd[t] = Bj[(c0 + t) * 65];
        }
#pragma unroll
        for (int r = 0; r < 2; r++) {
            *(float4*)&gZC[j * BSZ + (r0 + r) * BD + c0] =
                make_float4(m[r][0] * cd[0], m[r][1] * cd[1],
                            m[r][2] * cd[2], m[r][3] * cd[3]);
            *(float4*)&gZB[j * BSZ + (r0 + r) * BD + c0] =
                make_float4(m[r][0] * bd[0], m[r][1] * bd[1],
                            m[r][2] * bd[2], m[r][3] * bd[3]);
        }
    } else if (mode == 1) {
        // levels 2-6: store Ainv; kZ forms ZC/ZB in parallel CTAs
#pragma unroll
        for (int r = 0; r < 2; r++)
            *(float4*)&gAi[j * BSZ + (r0 + r) * BD + c0] =
                make_float4(m[r][0], m[r][1], m[r][2], m[r][3]);
    }
    // mode 2: Zy only
}

// ---------------------------------------------------------------------------
// kZ: ZC = Ainv * C (by=0) or ZB = Ainv * B (by=1). One 64^3 GEMM per CTA,
// Ainv staged in smem (pad 65: conflict-free row reads), C/B streamed via
// __ldg column panels (warp-uniform -> broadcast).
// ---------------------------------------------------------------------------
__global__ void __launch_bounds__(512, 1)
kZ(int s, int p)
{
    const int j     = s - 1 + 2 * s * blockIdx.x;
    const int which = blockIdx.y;
    const int tid   = threadIdx.x;
    const int rg    = tid & 31;
    const int cg    = tid >> 5;
    const int c0    = 4 * cg;
    const int r0    = 2 * rg;

    const float* src = (which ? gBb[p] : gCb[p]) + j * BSZ;
    float*       dst = (which ? gZB    : gZC)    + j * BSZ;

    __shared__ float sAi[64 * 65];
    for (int e = tid; e < BSZ; e += 512) {
        int r = e >> 6, c = e & 63;
        sAi[r * 65 + c] = gAi[j * BSZ + e];
    }
    __syncthreads();

    float4 acc0 = make_float4(0.f, 0.f, 0.f, 0.f);
    float4 acc1 = acc0;
#pragma unroll 4
    for (int k = 0; k < 64; k++) {
        float a0 = sAi[r0 * 65 + k];
        float a1 = sAi[(r0 + 1) * 65 + k];
        float4 v = __ldg((const float4*)&src[k * BD + c0]);
        acc0.x += a0 * v.x; acc0.y += a0 * v.y;
        acc0.z += a0 * v.z; acc0.w += a0 * v.w;
        acc1.x += a1 * v.x; acc1.y += a1 * v.y;
        acc1.z += a1 * v.z; acc1.w += a1 * v.w;
    }
    *(float4*)&dst[r0 * BD + c0]       = acc0;
    *(float4*)&dst[(r0 + 1) * BD + c0] = acc1;
}

// ---------------------------------------------------------------------------
// K2 level 1: C_i, B_i diagonal -> all Schur updates are row scalings.
// ---------------------------------------------------------------------------
__global__ void __launch_bounds__(256, 1)
k2_lvl1()
{
    const int i   = 1 + 2 * blockIdx.x;
    const int jm  = i - 1;
    const int jp  = (i + 1 > 63) ? 63 : (i + 1);
    const int tid = threadIdx.x;

    __shared__ float scd[64], sbd[64];
    if (tid < 64) {
        scd[tid] = gCb[0][i * BSZ + tid * 65];
        sbd[tid] = gBb[0][i * BSZ + tid * 65];
    }
    __syncthreads();

    for (int e = tid; e < 1024; e += 256) {
        int r  = e >> 4;
        int c4 = (e & 15) << 2;
        float cdr = scd[r], bdr = sbd[r];
        int off = r * BD + c4;

        float4 zbm = *(const float4*)&gZB[jm * BSZ + off];
        float4 zcp = *(const float4*)&gZC[jp * BSZ + off];
        float4 a   = *(const float4*)&gA [i * BSZ + off];
        a.x -= cdr * zbm.x + bdr * zcp.x;
        a.y -= cdr * zbm.y + bdr * zcp.y;
        a.z -= cdr * zbm.z + bdr * zcp.z;
        a.w -= cdr * zbm.w + bdr * zcp.w;
        *(float4*)&gA[i * BSZ + off] = a;

        float4 zcm = *(const float4*)&gZC[jm * BSZ + off];
        *(float4*)&gCb[1][i * BSZ + off] =
            make_float4(-cdr * zcm.x, -cdr * zcm.y, -cdr * zcm.z, -cdr * zcm.w);
        float4 zbp = *(const float4*)&gZB[jp * BSZ + off];
        *(float4*)&gBb[1][i * BSZ + off] =
            make_float4(-bdr * zbp.x, -bdr * zbp.y, -bdr * zbp.z, -bdr * zbp.w);
    }
    if (tid < 64)
        gy[i * BD + tid] -= scd[tid] * gZy[jm * BD + tid]
                          + sbd[tid] * gZy[jp * BD + tid];
}

// ---------------------------------------------------------------------------
// K2 (levels >= 2): 5 balanced tasks per surviving block i:
//   task 0/1: A[:, half] -= C*ZB_jm[:,half] + B*ZC_jp[:,half]
//   task 2:   C' = -C*ZC_jm        task 3: B' = -B*ZB_jp
//   task 4:   y -= C*Zy_jm + B*Zy_jp
// ---------------------------------------------------------------------------
#define K2_SMEM (4 * 64 * 68 * 4)

__global__ void __launch_bounds__(256, 1)
k2_update(int s, int p)
{
    const int i    = 2 * s - 1 + 2 * s * blockIdx.x;
    const int task = blockIdx.y;
    const int jm   = i - s;
    const int jp   = (i + s > 63) ? 63 : (i + s);
    const int tid  = threadIdx.x;

    if (task == 4) {
        __shared__ float sy1[64], sy2[64];
        if (tid < 64) { sy1[tid] = gZy[jm * BD + tid]; sy2[tid] = gZy[jp * BD + tid]; }
        __syncthreads();
        if (tid < 64) {
            float acc = gy[i * BD + tid];
            const float* cp = gCb[p] + i * BSZ + tid * BD;
            const float* bp = gBb[p] + i * BSZ + tid * BD;
#pragma unroll 8
            for (int b = 0; b < 64; b++) acc -= cp[b] * sy1[b] + bp[b] * sy2[b];
            gy[i * BD + tid] = acc;
        }
        return;
    }

    extern __shared__ float sm2[];

    if (task < 2) {
        // ---- A column-half update ---------------------------------------
        const int coff = task << 5;
        float* P1 = sm2;                  // C_i  [64][68]
        float* P2 = sm2 + 64 * 68;        // B_i  [64][68]
        float* Q1 = sm2 + 2 * 64 * 68;            // ZB_jm panel [64][34]
        float* Q2 = sm2 + 2 * 64 * 68 + 64 * 34;  // ZC_jp panel [64][34]

        const float* Cg  = gCb[p] + i * BSZ;
        const float* Bg  = gBb[p] + i * BSZ;
        const float* ZBm = gZB + jm * BSZ;
        const float* ZCp = gZC + jp * BSZ;

        for (int e = tid; e < BSZ; e += 256) {
            int r = e >> 6, c = e & 63;
            P1[r * 68 + c] = Cg[e];
            P2[r * 68 + c] = Bg[e];
        }
        for (int e = tid; e < 2048; e += 256) {
            int k = e >> 5, c = e & 31;
            Q1[k * 34 + c] = ZBm[k * BD + coff + c];
            Q2[k * 34 + c] = ZCp[k * BD + coff + c];
        }
        __syncthreads();

        const int r0 = (tid >> 4) << 2;
        const int c2 = (tid & 15) << 1;
        float acc[4][2];
#pragma unroll
        for (int u = 0; u < 4; u++) { acc[u][0] = 0.f; acc[u][1] = 0.f; }

        for (int k = 0; k < 64; k++) {
            float2 b1 = *(const float2*)&Q1[k * 34 + c2];
            float2 b2 = *(const float2*)&Q2[k * 34 + c2];
#pragma unroll
            for (int u = 0; u < 4; u++) {
                float a1 = P1[(r0 + u) * 68 + k];
                float a2 = P2[(r0 + u) * 68 + k];
                acc[u][0] += a1 * b1.x + a2 * b2.x;
                acc[u][1] += a1 * b1.y + a2 * b2.y;
            }
        }
#pragma unroll
        for (int u = 0; u < 4; u++) {
            float2 o = *(float2*)&gA[i * BSZ + (r0 + u) * BD + coff + c2];
            o.x -= acc[u][0]; o.y -= acc[u][1];
            *(float2*)&gA[i * BSZ + (r0 + u) * BD + coff + c2] = o;
        }
        return;
    }

    // ---- task 2/3: full-width single-product C'/B' ----------------------
    float* P1 = sm2;
    float* Q1 = sm2 + 64 * 68;

    const float* p1g = ((task == 2) ? gCb[p] : gBb[p]) + i * BSZ;
    const float* q1g = (task == 2) ? (gZC + jm * BSZ) : (gZB + jp * BSZ);

    for (int e = tid; e < BSZ; e += 256) {
        int r = e >> 6, c = e & 63;
        P1[r * 68 + c] = p1g[e];
        Q1[r * 68 + c] = q1g[e];
    }
    __syncthreads();

    const int r0 = (tid >> 4) << 2;
    const int cc = (tid & 15) << 2;
    float acc[4][4];
#pragma unroll
    for (int u = 0; u < 4; u++)
#pragma unroll
        for (int v = 0; v < 4; v++) acc[u][v] = 0.0f;

    for (int k = 0; k < 64; k++) {
        float4 b1 = *(const float4*)&Q1[k * 68 + cc];
#pragma unroll
        for (int u = 0; u < 4; u++) {
            float a1 = P1[(r0 + u) * 68 + k];
            acc[u][0] += a1 * b1.x;
            acc[u][1] += a1 * b1.y;
            acc[u][2] += a1 * b1.z;
            acc[u][3] += a1 * b1.w;
        }
    }
    float* dst = ((task == 2) ? gCb[p ^ 1] : gBb[p ^ 1]) + i * BSZ;
#pragma unroll
    for (int u = 0; u < 4; u++)
        *(float4*)&dst[(r0 + u) * BD + cc] =
            make_float4(-acc[u][0], -acc[u][1], -acc[u][2], -acc[u][3]);
}

// ---------------------------------------------------------------------------
// Backsub (unchanged)
// ---------------------------------------------------------------------------
__global__ void __launch_bounds__(1024, 1)
backsub_kernel(float* __restrict__ out)
{
    __shared__ float sx[NBLK * BD];
    const int tid = threadIdx.x;
    for (int e = tid; e < NBLK * BD; e += 1024) sx[e] = 0.0f;
    __syncthreads();

    for (int lev = 7; lev >= 1; lev--) {
        int s  = 1 << (lev - 1);
        int ne = (lev == 7) ? 1 : (32 >> (lev - 1));
        for (int idx = tid; idx < ne * 64; idx += 1024) {
            int t = idx >> 6, a = idx & 63;
            int j = s - 1 + 2 * s * t;
            int jm = j - s; if (jm < 0)  jm = 0;
            int jp = j + s; if (jp > 63) jp = 63;
            const float4* zc = (const float4*)(gZC + j * BSZ + a * BD);
            const float4* zb = (const float4*)(gZB + j * BSZ + a * BD);
            float s0 = 0.f, s1 = 0.f, s2 = 0.f, s3 = 0.f;
#pragma unroll
            for (int w = 0; w < 16; w++) {
                float4 c4 = zc[w], b4 = zb[w];
                s0 += c4.x * sx[jm * BD + 4 * w]     + b4.x * sx[jp * BD + 4 * w];
                s1 += c4.y * sx[jm * BD + 4 * w + 1] + b4.y * sx[jp * BD + 4 * w + 1];
                s2 += c4.z * sx[jm * BD + 4 * w + 2] + b4.z * sx[jp * BD + 4 * w + 2];
                s3 += c4.w * sx[jm * BD + 4 * w + 3] + b4.w * sx[jp * BD + 4 * w + 3];
            }
            float acc = gZy[j * BD + a] - (s0 + s1 + s2 + s3);
            sx[j * BD + a]  = acc;
            out[j * BD + a] = acc;
        }
        __syncthreads();
    }
}

// ---------------------------------------------------------------------------
// kernel_launch
// ---------------------------------------------------------------------------
extern "C" void kernel_launch(void* const* d_in, const int* in_sizes, int n_in,
                              void* d_out, int out_size)
{
    const float* h    = (const float*)d_in[0];
    const float* phi  = (const float*)d_in[1];
    const float* base = (const float*)d_in[2];
    const float* over = (const float*)d_in[3];
    const float* melt = (const float*)d_in[4];
    const float* len  = (const float*)d_in[5];
    const int*   adj  = (const int*)  d_in[6];
    const int*   io   = (const int*)  d_in[7];
    float* out = (float*)d_out;

    static int once = []() {
        cudaFuncSetAttribute(k2_update,
                             cudaFuncAttributeMaxDynamicSharedMemorySize,
                             K2_SMEM);
        return 0;
    }();
    (void)once;

    assemble_kernel<<<32, 128>>>(h, phi, base, over, melt, len, adj, io);

    // level 1: eliminate even blocks; diagonal C/B specializations
    k1inv<<<32, 512>>>(1, /*mode=*/0);
    k2_lvl1<<<32, 256>>>();

    // levels 2..6
    for (int lev = 2; lev <= 6; lev++) {
        int s = 1 << (lev - 1);
        int n = 32 >> (lev - 1);
        int p = (lev - 1) & 1;
        k1inv<<<n, 512>>>(s, /*mode=*/1);
        kZ<<<dim3(n, 2), 512>>>(s, p);
        k2_update<<<dim3(n, 5), 256, K2_SMEM>>>(s, p);
    }

    // top block (j = 63): only Zy needed
    k1inv<<<1, 512>>>(64, /*mode=*/2);
    backsub_kernel<<<1, 1024>>>(out);
}